// round 17
// baseline (speedup 1.0000x reference)
#include <cuda_runtime.h>
#include <cstdint>

// Problem constants
#define B   32
#define C   256
#define H   56
#define W   56
#define OH  28
#define OW  28
#define CO  256           // outputs per half
#define NW  8             // 256 bits -> 8 uint32 words
#define NELEM_PER_C (B*H*W)  // 100352

// -------- device scratch (no allocations allowed) --------
__device__ float    g_partial[C][B][2];          // per (channel, batch): sum, sumsq
__device__ float    g_lo[C];                     // binarize window: +1 iff lo <= v <= hi
__device__ float    g_hi[C];
__device__ int      g_fast;                      // 1 if all gamma > 0 (lo-only compare)
__device__ unsigned g_wpack[2*CO][NW];           // rows 0..255 = w1, 256..511 = w2
__device__ unsigned g_count;                     // stats-block arrival counter (reset each run)

// ============================================================
// Kernel 1: stats partials (one warp per TWO adjacent channel planes)
// + weight pack + LAST-BLOCK threshold finalize.
// grid 576: blocks 0..511 stats (4096 warps x 2 planes), 512..575 wpack.
// Half-size resident footprint (~4 blocks/SM) leaves SM slots free so the
// PDL-launched fused kernel co-resides and preloads x during stats.
// ============================================================
__global__ __launch_bounds__(256) void stats_wpack_kernel(const float* __restrict__ x,
                                                          const float* __restrict__ w1,
                                                          const float* __restrict__ w2,
                                                          const float* __restrict__ gamma,
                                                          const float* __restrict__ beta) {
    cudaTriggerProgrammaticLaunchCompletion();

    int lane = threadIdx.x & 31;
    if (blockIdx.x >= 512) {
        int warp = ((blockIdx.x - 512) * 256 + threadIdx.x) >> 5;   // 0..511
        const float* w = (warp < CO) ? (w1 + (size_t)warp * C)
                                     : (w2 + (size_t)(warp - CO) * C);
        #pragma unroll
        for (int j = 0; j < NW; j++) {
            float v = w[j * 32 + lane];
            unsigned m = __ballot_sync(0xffffffffu, v >= 0.f);
            if (lane == 0) g_wpack[warp][j] = m;
        }
        return;
    }
    // ---- stats: warp wid handles planes 2*wid and 2*wid+1 (same b, c & c+1) ----
    int wid = (blockIdx.x * 256 + threadIdx.x) >> 5;  // 0..4095
    int b  = wid >> 7;            // (2*wid)>>8
    int c0 = (2 * wid) & 255;     // even channel
    const float4* pA = reinterpret_cast<const float4*>(x + ((size_t)b * C + c0) * (H * W));
    const float4* pB = pA + (H * W) / 4;   // next channel plane
    float sA0 = 0.f, qA0 = 0.f, sB0 = 0.f, qB0 = 0.f;
    #pragma unroll 4
    for (int it = 0; it < 24; it++) {
        float4 a = pA[lane + it * 32];
        float4 d = pB[lane + it * 32];
        sA0 += (a.x + a.y) + (a.z + a.w);
        qA0 += (a.x * a.x + a.y * a.y) + (a.z * a.z + a.w * a.w);
        sB0 += (d.x + d.y) + (d.z + d.w);
        qB0 += (d.x * d.x + d.y * d.y) + (d.z * d.z + d.w * d.w);
    }
    if (lane < 16) {
        float4 a = pA[lane + 768];
        float4 d = pB[lane + 768];
        sA0 += (a.x + a.y) + (a.z + a.w);
        qA0 += (a.x * a.x + a.y * a.y) + (a.z * a.z + a.w * a.w);
        sB0 += (d.x + d.y) + (d.z + d.w);
        qB0 += (d.x * d.x + d.y * d.y) + (d.z * d.z + d.w * d.w);
    }
    #pragma unroll
    for (int o = 16; o > 0; o >>= 1) {
        sA0 += __shfl_down_sync(0xffffffffu, sA0, o);
        qA0 += __shfl_down_sync(0xffffffffu, qA0, o);
        sB0 += __shfl_down_sync(0xffffffffu, sB0, o);
        qB0 += __shfl_down_sync(0xffffffffu, qB0, o);
    }
    if (lane == 0) {
        g_partial[c0][b][0] = sA0;
        g_partial[c0][b][1] = qA0;
        g_partial[c0 + 1][b][0] = sB0;
        g_partial[c0 + 1][b][1] = qB0;
    }

    // ---- last-arriving stats block finalizes thresholds ----
    __threadfence();
    __shared__ int is_last;
    if (threadIdx.x == 0)
        is_last = (atomicAdd(&g_count, 1u) == 511u);
    __syncthreads();
    if (!is_last) return;

    {
        int c2 = threadIdx.x;                     // 256 threads = 256 channels
        float ss = 0.f, sq = 0.f;
        #pragma unroll
        for (int k = 0; k < B; k++) { ss += g_partial[c2][k][0]; sq += g_partial[c2][k][1]; }
        const float N = (float)NELEM_PER_C;
        float mean = ss / N;
        float var  = sq / N - mean * mean;
        if (var < 0.f) var = 0.f;
        float inv = rsqrtf(var + 1e-5f);
        float g = gamma[c2], bt = beta[c2];
        const float INF = __int_as_float(0x7f800000);
        float lo, hi;
        if (g > 0.f)      { lo = mean - bt / (inv * g); hi =  INF; }
        else if (g < 0.f) { hi = mean - bt / (inv * g); lo = -INF; }
        else if (bt >= 0.f) { lo = -INF; hi =  INF; }
        else                { lo =  INF; hi = -INF; }
        g_lo[c2] = lo;
        g_hi[c2] = hi;

        __shared__ int sflag;
        if (threadIdx.x == 0) sflag = 1;
        __syncthreads();
        unsigned warp_ok = __ballot_sync(0xffffffffu, g > 0.f);
        if ((threadIdx.x & 31) == 0 && warp_ok != 0xffffffffu) atomicAnd(&sflag, 0);
        __syncthreads();
        if (threadIdx.x == 0) {
            g_fast = sflag;
            g_count = 0;          // reset for next graph replay
        }
    }
}

// ============================================================
// Kernel 2 (FUSED): preload x BEFORE the PDL dependency sync, then
// weight-stage + binarize+pack, then XNOR-popcount GEMM.
// - x loads pre-sync (independent of kernel 1) overlap stats
// - weight-stage LDGs issued right after sync so their L2 latency hides
//   under the pack ALU work (instead of stalling at the barrier)
// - b reversed for L2 temporal locality with stats
// ============================================================
__global__ __launch_bounds__(256) void fused_kernel(const float* __restrict__ x,
                                                    float* __restrict__ out) {
    int oh = blockIdx.x, b = (B - 1) - blockIdx.y, half = blockIdx.z;
    int j    = threadIdx.x >> 5;
    int lane = threadIdx.x & 31;
    int h = 2 * oh + half;

    __shared__ uint4 sa4[OW * NW / 4];   // 896 B packed activations
    __shared__ uint4 sw4[CO * NW / 4];   // 8 KB packed weights (this half)
    unsigned* sa = reinterpret_cast<unsigned*>(sa4);

    // ---- pre-sync: issue ALL x loads (no kernel-1 dependency) ----
    float v[32];
    {
        const size_t rowstep = (size_t)H * W;
        int k = lane < OW ? lane : OW - 1;            // clamp so all lanes can shfl
        const float* base = x + (((size_t)b * C + j * 32) * H + h) * W;
        #pragma unroll
        for (int r = 0; r < 32; r++) {
            float2 t = __ldcg(reinterpret_cast<const float2*>(base + r * rowstep) + k);
            v[r] = half ? t.y : t.x;
        }
    }

    // ---- wait for stats_wpack_kernel's memory (thresholds, weights) ----
    cudaGridDependencySynchronize();

    // ---- stage weights first: LDG latency overlaps the pack ALU below ----
    {
        const uint4* wsrc = reinterpret_cast<const uint4*>(&g_wpack[half * CO][0]);
        uint4 w0 = wsrc[threadIdx.x];
        uint4 w1v = wsrc[threadIdx.x + 256];
        sw4[threadIdx.x] = w0;
        sw4[threadIdx.x + 256] = w1v;
    }

    // ---- Phase A: compare + register-pack (data already in regs) ----
    {
        unsigned bits = 0;
        if (g_fast) {
            float lo_mine = g_lo[j * 32 + lane];      // one value per lane
            #pragma unroll
            for (int r = 0; r < 32; r++) {
                float lo_r = __shfl_sync(0xffffffffu, lo_mine, r);
                bits |= (v[r] >= lo_r ? 1u : 0u) << r;
            }
        } else {
            float lo_mine = g_lo[j * 32 + lane];
            float hi_mine = g_hi[j * 32 + lane];
            #pragma unroll
            for (int r = 0; r < 32; r++) {
                float lo_r = __shfl_sync(0xffffffffu, lo_mine, r);
                float hi_r = __shfl_sync(0xffffffffu, hi_mine, r);
                bool pred = (v[r] >= lo_r) && (v[r] <= hi_r);
                bits |= (pred ? 1u : 0u) << r;
            }
        }
        if (lane < OW) sa[lane * NW + j] = bits;
    }
    __syncthreads();

    // ---- Phase B: popcount GEMM (vector LDS) ----
    if (lane >= OW) return;

    uint4 av0 = sa4[lane * 2 + 0];
    uint4 av1 = sa4[lane * 2 + 1];
    unsigned a0 = av0.x, a1 = av0.y, a2 = av0.z, a3 = av0.w;
    unsigned a4 = av1.x, a5 = av1.y, a6 = av1.z, a7 = av1.w;

    float* op = out + ((((size_t)b * 2 * CO + half * CO) * OH + oh) * OW) + lane;
    #pragma unroll 8
    for (int oo = 0; oo < CO / 8; oo++) {
        int o = oo * 8 + j;
        uint4 wv0 = sw4[o * 2 + 0];
        uint4 wv1 = sw4[o * 2 + 1];
        int s = __popc(a0 ^ wv0.x) + __popc(a1 ^ wv0.y)
              + __popc(a2 ^ wv0.z) + __popc(a3 ^ wv0.w)
              + __popc(a4 ^ wv1.x) + __popc(a5 ^ wv1.y)
              + __popc(a6 ^ wv1.z) + __popc(a7 ^ wv1.w);
        op[(size_t)o * (OH * OW)] = (float)(C - 2 * s);
    }
}

// ============================================================
extern "C" void kernel_launch(void* const* d_in, const int* in_sizes, int n_in,
                              void* d_out, int out_size) {
    const float* x     = (const float*)d_in[0];
    const float* gamma = (const float*)d_in[1];
    const float* beta  = (const float*)d_in[2];
    const float* w1    = (const float*)d_in[3];
    const float* w2    = (const float*)d_in[4];
    float* out = (float*)d_out;

    stats_wpack_kernel<<<576, 256>>>(x, w1, w2, gamma, beta);

    // PDL launch of fused: blocks co-reside with stats (its footprint is
    // halved) and preload x; gridDependencySynchronize preserves the
    // data dependency on thresholds/weights.
    cudaLaunchConfig_t cfg = {};
    cfg.gridDim  = dim3(OH, B, 2);
    cfg.blockDim = dim3(256, 1, 1);
    cudaLaunchAttribute attrs[1];
    attrs[0].id = cudaLaunchAttributeProgrammaticStreamSerialization;
    attrs[0].val.programmaticStreamSerializationAllowed = 1;
    cfg.attrs = attrs;
    cfg.numAttrs = 1;
    cudaError_t e = cudaLaunchKernelEx(&cfg, fused_kernel, x, out);
    if (e != cudaSuccess) {
        (void)cudaGetLastError();   // clear; fall back to plain launch
        fused_kernel<<<dim3(OH, B, 2), 256>>>(x, out);
    }
}